// round 9
// baseline (speedup 1.0000x reference)
#include <cuda_runtime.h>
#include <cuda_fp16.h>
#include <mma.h>
#include <cstdint>

using namespace nvcuda;

#define NN 100000
#define NE 600000
#define D  128
#define CAP 64
#define NT 782            // ceil(100000 / 128)
#define GRID 148

// ---------------- device scratch ----------------
__device__ int    g_cnt[NN];
__device__ uint2  g_bucket[(size_t)NN * CAP];   // (src, weight_bits)
__device__ __half g_wt[2 * D * D];              // fp16 [Wl ; Wr]  (K-row major [256][128])

// ---------------- cp.async helpers ----------------
__device__ __forceinline__ void cp_async16(uint32_t dst, const void* src) {
    asm volatile("cp.async.cg.shared.global [%0], [%1], 16;"
                 :: "r"(dst), "l"(src) : "memory");
}
#define CP_COMMIT() asm volatile("cp.async.commit_group;" ::: "memory")
#define CP_WAIT(n)  asm volatile("cp.async.wait_group %0;" :: "n"(n) : "memory")

// ---------------- prep: zero counters + convert weights to fp16 ----------------
__global__ void __launch_bounds__(256) prep_kernel(
    const float* __restrict__ wl, const float* __restrict__ wr)
{
    int i = blockIdx.x * 256 + threadIdx.x;
    if (i < NN) g_cnt[i] = 0;
    if (i < D * D) {
        g_wt[i]         = __float2half_rn(wl[i]);
        g_wt[D * D + i] = __float2half_rn(wr[i]);
    }
}

// ---------------- scatter edges into buckets ----------------
__global__ void __launch_bounds__(256) scatter_kernel(
    const int* __restrict__ esrc,
    const int* __restrict__ edst,
    const float* __restrict__ ew)
{
    int e = blockIdx.x * 256 + threadIdx.x;
    if (e >= NE) return;
    int s = __ldg(&esrc[e]);
    int d = __ldg(&edst[e]);
    float w = __ldg(&ew[e]);
    int pos = atomicAdd(&g_cnt[d], 1);
    g_bucket[(size_t)d * CAP + pos] = make_uint2((unsigned)s, __float_as_uint(w));
}

// ---------------- persistent warp-specialized gather + dual fp16 GEMM ----------
#define BM 128
#define LDA 136     // halves
#define LDB 136     // halves
#define LDBI 136    // floats

// smem byte offsets
#define OFF_AGG  0                                   // [2][128][LDA] half = 69632
#define OFF_X    69632                               // [2][128][LDA] half = 69632
#define OFF_B    139264                              // [256][LDB]   half = 69632
#define OFF_BIAS 208896                              // [16][LDBI]   f32  = 8704
#define SM_BYTES 217600

__global__ void __launch_bounds__(512, 1) fused_kernel(
    const float* __restrict__ x,
    const float* __restrict__ bl,
    const float* __restrict__ br,
    float* __restrict__ out)
{
    extern __shared__ char smraw[];
    __half* AsAgg = (__half*)(smraw + OFF_AGG);   // [2][128][LDA]
    __half* AsX   = (__half*)(smraw + OFF_X);     // [2][128][LDA]
    __half* Bsm   = (__half*)(smraw + OFF_B);     // [256][LDB]
    float*  Bias  = (float*) (smraw + OFF_BIAS);  // [16][LDBI]

    const int tid  = threadIdx.x;
    const int wid  = tid >> 5;
    const int lane = tid & 31;
    const int bid  = blockIdx.x;
    const int n_tiles = (NT - bid + GRID - 1) / GRID;

    // ---- everyone: issue resident B load (64KB) ----
    {
        uint32_t b_base = (uint32_t)__cvta_generic_to_shared(Bsm);
        const int c8 = (tid & 15) * 8;       // halves 0..120
        const int r0 = tid >> 4;             // 0..31
        #pragma unroll
        for (int it = 0; it < 8; it++) {
            int row = r0 + it * 32;          // 0..255
            cp_async16(b_base + (row * LDB + c8) * 2,
                       &g_wt[(size_t)row * D + c8]);
        }
        CP_COMMIT();
    }

    // ---- gather-warp tile fill: agg rows + x rows (fp32 acc -> fp16) ----
    auto fill_tile = [&](int t, int buf) {
        const int gw = wid - 8;              // 0..7
        const int m0 = t * BM;
        __half* agg_buf = AsAgg + (size_t)buf * BM * LDA;
        __half* x_buf   = AsX   + (size_t)buf * BM * LDA;
        for (int i = 0; i < 16; i++) {
            int row = gw * 16 + i;
            int n = m0 + row;
            float4 a0 = make_float4(0.f, 0.f, 0.f, 0.f);
            float4 a1 = a0;
            float4 xv = a0;
            if (n < NN) {
                xv = *(const float4*)&x[(size_t)n * D + lane * 4];
                int deg = __ldg(&g_cnt[n]);
                const uint2* bk = &g_bucket[(size_t)n * CAP];
                int j = 0;
                for (; j + 2 <= deg; j += 2) {
                    uint2 e0 = __ldg(&bk[j]);
                    uint2 e1 = __ldg(&bk[j + 1]);
                    float w0 = __uint_as_float(e0.y);
                    float w1 = __uint_as_float(e1.y);
                    float4 v0 = *(const float4*)&x[(size_t)e0.x * D + lane * 4];
                    float4 v1 = *(const float4*)&x[(size_t)e1.x * D + lane * 4];
                    a0.x += w0 * v0.x; a0.y += w0 * v0.y;
                    a0.z += w0 * v0.z; a0.w += w0 * v0.w;
                    a1.x += w1 * v1.x; a1.y += w1 * v1.y;
                    a1.z += w1 * v1.z; a1.w += w1 * v1.w;
                }
                if (j < deg) {
                    uint2 e0 = __ldg(&bk[j]);
                    float w0 = __uint_as_float(e0.y);
                    float4 v0 = *(const float4*)&x[(size_t)e0.x * D + lane * 4];
                    a0.x += w0 * v0.x; a0.y += w0 * v0.y;
                    a0.z += w0 * v0.z; a0.w += w0 * v0.w;
                }
            }
            a0.x += a1.x; a0.y += a1.y; a0.z += a1.z; a0.w += a1.w;
            __half2* da = (__half2*)&agg_buf[row * LDA + lane * 4];
            da[0] = __floats2half2_rn(a0.x, a0.y);
            da[1] = __floats2half2_rn(a0.z, a0.w);
            __half2* dx = (__half2*)&x_buf[row * LDA + lane * 4];
            dx[0] = __floats2half2_rn(xv.x, xv.y);
            dx[1] = __floats2half2_rn(xv.z, xv.w);
        }
    };

    // ---- compute-warp tile GEMM + store ----
    const int warp_m = wid & 3;
    const int warp_n = (wid >> 2) & 1;
    auto do_tile = [&](int t, int buf) {
        const int m0 = t * BM;
        const __half* agg_buf = AsAgg + (size_t)buf * BM * LDA;
        const __half* x_buf   = AsX   + (size_t)buf * BM * LDA;

        wmma::fragment<wmma::accumulator, 16, 16, 16, float> acc[2][4];
        #pragma unroll
        for (int i = 0; i < 2; i++)
            #pragma unroll
            for (int j = 0; j < 4; j++)
                wmma::load_matrix_sync(acc[i][j], &Bias[warp_n * 64 + j * 16], LDBI,
                                       wmma::mem_row_major);

        #pragma unroll
        for (int half_sel = 0; half_sel < 2; half_sel++) {
            const __half* a_src = half_sel ? x_buf : agg_buf;
            const int kbase = half_sel * 128;
            #pragma unroll
            for (int kc = 0; kc < 8; kc++) {
                wmma::fragment<wmma::matrix_a, 16, 16, 16, __half, wmma::row_major> af[2];
                #pragma unroll
                for (int i = 0; i < 2; i++)
                    wmma::load_matrix_sync(af[i],
                        &a_src[(warp_m * 32 + i * 16) * LDA + kc * 16], LDA);
                #pragma unroll
                for (int j = 0; j < 4; j++) {
                    wmma::fragment<wmma::matrix_b, 16, 16, 16, __half, wmma::row_major> bf;
                    wmma::load_matrix_sync(bf,
                        &Bsm[(size_t)(kbase + kc * 16) * LDB + warp_n * 64 + j * 16], LDB);
                    #pragma unroll
                    for (int i = 0; i < 2; i++)
                        wmma::mma_sync(acc[i][j], af[i], bf, acc[i][j]);
                }
            }
        }

        #pragma unroll
        for (int i = 0; i < 2; i++) {
            int row0 = m0 + warp_m * 32 + i * 16;
            if (row0 >= NN) continue;
            #pragma unroll
            for (int j = 0; j < 4; j++) {
                int col0 = warp_n * 64 + j * 16;
                wmma::store_matrix_sync(&out[(size_t)row0 * D + col0], acc[i][j], D,
                                        wmma::mem_row_major);
            }
        }
    };

    // ---- prologue ----
    if (wid >= 8) {
        fill_tile(bid, 0);
    } else {
        // bias replica tile (compute warps, tids 0..255)
        for (int s = tid; s < 16 * LDBI; s += 256) {
            int c = s % LDBI;
            Bias[s] = (c < 128) ? (bl[c] + br[c]) : 0.f;
        }
    }
    CP_WAIT(0);
    __syncthreads();

    // ---- pipelined main loop ----
    for (int i = 0; i < n_tiles; i++) {
        if (wid < 8) {
            do_tile(bid + i * GRID, i & 1);
        } else if (i + 1 < n_tiles) {
            fill_tile(bid + (i + 1) * GRID, (i + 1) & 1);
        }
        __syncthreads();
    }
}

// ---------------- launch ----------------
extern "C" void kernel_launch(void* const* d_in, const int* in_sizes, int n_in,
                              void* d_out, int out_size)
{
    const float* x    = (const float*)d_in[0];
    const int*   esrc = (const int*)  d_in[1];
    const int*   edst = (const int*)  d_in[2];
    const float* ew   = (const float*)d_in[3];
    const float* wl   = (const float*)d_in[4];
    const float* bl   = (const float*)d_in[5];
    const float* wr   = (const float*)d_in[6];
    const float* br   = (const float*)d_in[7];
    float* out = (float*)d_out;

    static bool attr_set = false;
    if (!attr_set) {
        cudaFuncSetAttribute(fused_kernel,
                             cudaFuncAttributeMaxDynamicSharedMemorySize, SM_BYTES);
        attr_set = true;
    }

    prep_kernel<<<(NN + 255) / 256, 256>>>(wl, wr);
    scatter_kernel<<<(NE + 255) / 256, 256>>>(esrc, edst, ew);
    fused_kernel<<<GRID, 512, SM_BYTES>>>(x, bl, br, out);
}